// round 12
// baseline (speedup 1.0000x reference)
#include <cuda_runtime.h>
#include <stdint.h>

#define NUM_HEADS 12
#define HEAD_DIM  64
#define HIDDEN    768
#define BATCH     2
#define SEQ       2048
#define M_TOTAL   (BATCH*SEQ)   // 4096
#define LOG2E     1.44269504f

// Q,K in [B,H,S,d] with d permuted within 16-groups (pos16); V TRANSPOSED
// [B,H,d,S] with key permuted within 16-groups. All tf32-rounded f32;
// Q pre-scaled by 0.125*log2(e).
__device__ float g_qkv[3][BATCH*NUM_HEADS*SEQ*HEAD_DIM];

__device__ __forceinline__ uint32_t f2tf32(float f) {
    uint32_t u;
    asm("cvt.rna.tf32.f32 %0, %1;" : "=r"(u) : "f"(f));
    return u;
}

__device__ __forceinline__ uint32_t u2tf32(uint32_t v) {
    uint32_t u;
    asm("cvt.rna.tf32.f32 %0, %1;" : "=r"(u) : "f"(__uint_as_float(v)));
    return u;
}

__device__ __forceinline__ float ex2(float f) {
    float r;
    asm("ex2.approx.f32 %0, %1;" : "=f"(r) : "f"(f));
    return r;
}

__device__ __forceinline__ void mma_tf32(float c[4], const uint32_t a[4],
                                         uint32_t b0, uint32_t b1) {
    asm volatile(
        "mma.sync.aligned.m16n8k8.row.col.f32.tf32.tf32.f32 "
        "{%0,%1,%2,%3}, {%4,%5,%6,%7}, {%8,%9}, {%0,%1,%2,%3};"
        : "+f"(c[0]), "+f"(c[1]), "+f"(c[2]), "+f"(c[3])
        : "r"(a[0]), "r"(a[1]), "r"(a[2]), "r"(a[3]), "r"(b0), "r"(b1));
}

__device__ __forceinline__ void ldsm_x4(uint32_t r[4], uint32_t addr) {
    asm volatile("ldmatrix.sync.aligned.m8n8.x4.shared.b16 {%0,%1,%2,%3}, [%4];"
        : "=r"(r[0]), "=r"(r[1]), "=r"(r[2]), "=r"(r[3]) : "r"(addr));
}

__device__ __forceinline__ void sts_v2(uint32_t addr, float a, float b) {
    asm volatile("st.shared.v2.f32 [%0], {%1,%2};" :: "r"(addr), "f"(a), "f"(b));
}

__device__ __forceinline__ void cpasync16(uint32_t dst, const void* src) {
    asm volatile("cp.async.cg.shared.global [%0], [%1], 16;" :: "r"(dst), "l"(src));
}
#define CP_COMMIT() asm volatile("cp.async.commit_group;")
#define CP_WAIT1()  asm volatile("cp.async.wait_group 1;")
#define CP_WAIT2()  asm volatile("cp.async.wait_group 2;")

// physical position of logical index r within its 16-group
__device__ __forceinline__ int pos16(int r) {
    return 4 * (r & 3) + 2 * (r >> 3) + ((r >> 2) & 1);
}
__device__ __forceinline__ int perm16(int d) {
    return (d & ~15) | pos16(d & 15);
}

// ---------------------------------------------------------------------------
// QKV projection v2b. BM=128, BN=64, BK=32; 256 threads, 8 warps = 4(m)x2(n).
// X: raw f32 cp.async double-buffered; A-frags via ldmatrix.x4.b16 then
// cvt.rna on the fragment registers (numerics identical to converting at
// store). W: register prefetch, cvt.rna at STS. Epilogues staged through
// smem -> coalesced STG.128.
// ---------------------------------------------------------------------------
__global__ __launch_bounds__(256, 2) void qkv_proj_kernel(
    const float* __restrict__ x,
    const float* __restrict__ Wq, const float* __restrict__ bq,
    const float* __restrict__ Wk, const float* __restrict__ bk,
    const float* __restrict__ Wv, const float* __restrict__ bv)
{
    const int z = blockIdx.z;
    const float* Wp   = (z == 0) ? Wq : (z == 1) ? Wk : Wv;
    const float* bias = (z == 0) ? bq : (z == 1) ? bk : bv;

    // union: mainloop Xs0|Xs1|Ws = 4608+4608+2304 = 11520 words (46080 B);
    // epilogue Es 128*68=8704 w  /  Ev 64*144=9216 w  (aliased)
    __shared__ uint32_t psm[11520];
    uint32_t* Ws = psm + 9216;

    const int tid  = threadIdx.x;
    const int lane = tid & 31;
    const int warp = tid >> 5;
    const int wm = warp >> 1;
    const int wn = warp & 1;
    const int m0 = blockIdx.x * 128;
    const int n0 = blockIdx.y * 64;
    const int h  = blockIdx.y;
    const int r0 = lane >> 2;
    const int q2 = lane & 3;

    const uint32_t sb = (uint32_t)__cvta_generic_to_shared(psm);

    // X cp.async mapping: row = tid>>1 (0..127), half-of-k = tid&1; 4x16B each
    const int xrow = tid >> 1, xc2 = tid & 1;
    const uint32_t xdst = sb + (uint32_t)(xrow * 144 + xc2 * 64);
    const char* xsrcb = (const char*)(x + (size_t)(m0 + xrow) * HIDDEN) + xc2 * 64;

    // W mapping: rows k = (tid>>4) + 16*it, cols (tid&15)*4 (coalesced LDG)
    const int wr_r = tid >> 4, wr_c = (tid & 15) * 4;

    // prologue: X(0) via cp.async, W(0) via regs
    #pragma unroll
    for (int j = 0; j < 4; ++j)
        cpasync16(xdst + j * 16, xsrcb + j * 16);
    CP_COMMIT();

    float4 wr[2];
    #pragma unroll
    for (int it = 0; it < 2; ++it)
        wr[it] = *(const float4*)(Wp + (size_t)(wr_r + it * 16) * HIDDEN + n0 + wr_c);

    // ldmatrix lane addressing
    const int lrow = (lane & 7) | ((lane >> 1) & 8);
    const int lcb  = (lane >> 3) & 1;

    float acc[2][4][4] = {};

    for (int t = 0; t < 24; ++t) {
        __syncthreads();    // prev iter's reads of Ws and Xs[(t+1)&1] done

        // store W(t) -> Ws with cvt.rna (STS.128, conflict-free)
        #pragma unroll
        for (int it = 0; it < 2; ++it) {
            uint4 u = { f2tf32(wr[it].x), f2tf32(wr[it].y),
                        f2tf32(wr[it].z), f2tf32(wr[it].w) };
            *(uint4*)&Ws[(wr_r + it * 16) * 72 + wr_c] = u;
        }

        // issue X(t+1) (wraps at end; harmless)
        {
            int kn = ((t + 1) % 24) * 32;
            uint32_t xb = xdst + (uint32_t)(((t + 1) & 1) ? 18432 : 0);
            const char* src = xsrcb + kn * 4;
            #pragma unroll
            for (int j = 0; j < 4; ++j)
                cpasync16(xb + j * 16, src + j * 16);
            CP_COMMIT();
        }
        CP_WAIT1();         // X(t) complete
        __syncthreads();

        // prefetch W(t+1) into regs (overlaps mma)
        {
            int kw = ((t + 1) % 24) * 32;
            #pragma unroll
            for (int it = 0; it < 2; ++it)
                wr[it] = *(const float4*)(Wp + (size_t)(kw + wr_r + it * 16) * HIDDEN + n0 + wr_c);
        }

        // mma (A-frags: ldmatrix then cvt.rna on registers)
        const uint32_t xb = sb + (uint32_t)((t & 1) ? 18432 : 0);
        #pragma unroll
        for (int ks = 0; ks < 4; ++ks) {
            uint32_t a[2][4];
            #pragma unroll
            for (int mt = 0; mt < 2; ++mt) {
                uint32_t R[4];
                ldsm_x4(R, xb + (uint32_t)((wm * 32 + mt * 16 + lrow) * 144 + ks * 32 + lcb * 16));
                a[mt][0] = u2tf32(R[0]); a[mt][1] = u2tf32(R[2]);
                a[mt][2] = u2tf32(R[1]); a[mt][3] = u2tf32(R[3]);
            }
            #pragma unroll
            for (int nt = 0; nt < 4; ++nt) {
                int Kr = ks * 8 + q2;
                int Cn = wn * 32 + nt * 8 + r0;
                uint32_t b0 = Ws[Kr * 72 + Cn];
                uint32_t b1 = Ws[(Kr + 4) * 72 + Cn];
                mma_tf32(acc[0][nt], a[0], b0, b1);
                mma_tf32(acc[1][nt], a[1], b0, b1);
            }
        }
    }
    __syncthreads();    // mainloop smem dead

    if (z != 2) {
        // ---- Q/K epilogue: stage [128][68] (cols perm16'd), coalesced out
        float* Es = (float*)psm;
        float* outg = g_qkv[z];
        const float scale = (z == 0) ? 0.125f * LOG2E : 1.0f;
        #pragma unroll
        for (int mt = 0; mt < 2; ++mt)
            #pragma unroll
            for (int nt = 0; nt < 4; ++nt) {
                int dcol = wn * 32 + nt * 8 + 2 * q2;
                int d0 = perm16(dcol), d1 = perm16(dcol + 1);
                float b0 = bias[n0 + dcol], b1 = bias[n0 + dcol + 1];
                #pragma unroll
                for (int half = 0; half < 2; ++half) {
                    int rowl = wm * 32 + mt * 16 + r0 + half * 8;
                    Es[rowl * 68 + d0] =
                        __uint_as_float(f2tf32((acc[mt][nt][half * 2 + 0] + b0) * scale));
                    Es[rowl * 68 + d1] =
                        __uint_as_float(f2tf32((acc[mt][nt][half * 2 + 1] + b1) * scale));
                }
            }
        __syncthreads();
        {
            int row = tid & 127, hf = tid >> 7;
            int m = m0 + row;
            int bI = m >> 11, sI = m & 2047;
            float* dst = outg + ((size_t)(bI * NUM_HEADS + h) * SEQ + sI) * 64 + hf * 32;
            #pragma unroll
            for (int i = 0; i < 8; ++i)
                *(float4*)(dst + i * 4) = *(float4*)&Es[row * 68 + hf * 32 + i * 4];
        }
    } else {
        // ---- V epilogue: stage transposed [64 d][144] (cols = perm16'd m)
        float* Ev = (float*)psm;
        #pragma unroll
        for (int mt = 0; mt < 2; ++mt)
            #pragma unroll
            for (int nt = 0; nt < 4; ++nt) {
                int dcol = wn * 32 + nt * 8 + 2 * q2;
                float b0 = bias[n0 + dcol], b1 = bias[n0 + dcol + 1];
                #pragma unroll
                for (int half = 0; half < 2; ++half) {
                    int mloc = wm * 32 + mt * 16 + r0 + half * 8;
                    int mp = (mloc & ~15) | pos16(mloc & 15);
                    Ev[dcol * 144 + mp] =
                        __uint_as_float(f2tf32(acc[mt][nt][half * 2 + 0] + b0));
                    Ev[(dcol + 1) * 144 + mp] =
                        __uint_as_float(f2tf32(acc[mt][nt][half * 2 + 1] + b1));
                }
            }
        __syncthreads();
        {
            int d = tid >> 2, g = tid & 3;
            int bI = m0 >> 11, sI0 = m0 & 2047;
            float* dst = g_qkv[2] + ((size_t)(bI * NUM_HEADS + h) * 64 + d) * SEQ + sI0;
            #pragma unroll
            for (int i = 0; i < 8; ++i)
                *(float4*)(dst + g * 4 + i * 16) = *(float4*)&Ev[d * 144 + g * 4 + i * 16];
        }
    }
}

// ---------------------------------------------------------------------------
// Flash attention (R10, unchanged): all-tf32, Br=64, 4 warps split
// (mh, nh); QK m32xn32, PV m32xd32; K double-buffered, V single-buffered;
// P through dead K(t) buffer via STS.64 + ldmatrix.b16.
// smem 61952B -> 3 CTAs/SM.
// ---------------------------------------------------------------------------
#define KSTR   80
#define KTILEB 20480      // 64*80*4
#define OFF_V  40960
#define OFF_LR 61440
#define SMEMB  61952

__global__ __launch_bounds__(128, 3) void attn_kernel(
    const float* __restrict__ mask,   // [B,1,1,S]
    float* __restrict__ out)          // [B,S,HIDDEN]
{
    extern __shared__ __align__(16) uint32_t sm[];

    const int tid  = threadIdx.x;
    const int lane = tid & 31;
    const int warp = tid >> 5;
    const int r0 = lane >> 2;
    const int q2 = lane & 3;
    const int mh = warp >> 1;
    const int nh = warp & 1;
    const int qbase = blockIdx.x * 64;
    const int bh = blockIdx.y;
    const int b  = bh / NUM_HEADS;
    const int h  = bh - b * NUM_HEADS;

    const float* Qg = g_qkv[0] + (size_t)bh * SEQ * 64;
    const float* Kg = g_qkv[1] + (size_t)bh * SEQ * 64;
    const float* Vg = g_qkv[2] + (size_t)bh * 64 * SEQ;
    const float2* mrow2base = (const float2*)(mask + (size_t)b * SEQ);

    const int rowk = tid >> 4;
    const int ch4  = (tid & 15) * 4;
    const uint32_t sbase = (uint32_t)__cvta_generic_to_shared(sm);
    const uint32_t kdst0 = sbase + (uint32_t)(rowk * KSTR + ch4) * 4;
    const uint32_t vdst  = sbase + OFF_V + (uint32_t)(rowk * KSTR + ch4) * 4;
    const float* ksrc0 = Kg + rowk * 64 + ch4;
    const float* vsrc0 = Vg + rowk * 2048 + ch4;

    #pragma unroll
    for (int i = 0; i < 8; ++i)
        cpasync16(kdst0 + i * (8 * KSTR * 4), ksrc0 + i * 512);
    CP_COMMIT();
    #pragma unroll
    for (int i = 0; i < 8; ++i)
        cpasync16(vdst + i * (8 * KSTR * 4), vsrc0 + i * 16384);
    CP_COMMIT();
    #pragma unroll
    for (int i = 0; i < 8; ++i)
        cpasync16(kdst0 + KTILEB + i * (8 * KSTR * 4), ksrc0 + 4096 + i * 512);
    CP_COMMIT();

    uint32_t Qa[2][8][4];
    #pragma unroll
    for (int mt = 0; mt < 2; ++mt) {
        const float* qp = Qg + (size_t)(qbase + mh * 32 + mt * 16 + r0) * 64;
        #pragma unroll
        for (int g = 0; g < 4; ++g) {
            float4 lo = *(const float4*)(qp + g * 16 + q2 * 4);
            float4 hi = *(const float4*)(qp + 512 + g * 16 + q2 * 4);
            Qa[mt][2*g][0]   = __float_as_uint(lo.x);
            Qa[mt][2*g][2]   = __float_as_uint(lo.y);
            Qa[mt][2*g+1][0] = __float_as_uint(lo.z);
            Qa[mt][2*g+1][2] = __float_as_uint(lo.w);
            Qa[mt][2*g][1]   = __float_as_uint(hi.x);
            Qa[mt][2*g][3]   = __float_as_uint(hi.y);
            Qa[mt][2*g+1][1] = __float_as_uint(hi.z);
            Qa[mt][2*g+1][3] = __float_as_uint(hi.w);
        }
    }

    float accO[2][4][4] = {};
    float lr[2][2] = {};

    const int  lrow  = (lane & 7) | ((lane >> 1) & 8);
    const int  lcb   = (lane >> 3) & 1;
    const uint32_t xr_st = (uint32_t)((r0 & 4) << 2);
    const uint32_t xr_ld = (uint32_t)((lrow & 4) << 2);

    for (int t = 0; t < 32; ++t) {
        CP_WAIT2();
        __syncthreads();

        const uint32_t* Kb = sm + ((t & 1) ? KTILEB : 0) / 4;
        float s[2][4][4] = {};
        #pragma unroll
        for (int g = 0; g < 4; ++g)
            #pragma unroll
            for (int ntl = 0; ntl < 4; ++ntl) {
                uint4 u = *(const uint4*)&Kb[(nh * 32 + ntl * 8 + r0) * KSTR + g * 16 + q2 * 4];
                mma_tf32(s[0][ntl], Qa[0][2*g],   u.x, u.y);
                mma_tf32(s[0][ntl], Qa[0][2*g+1], u.z, u.w);
                mma_tf32(s[1][ntl], Qa[1][2*g],   u.x, u.y);
                mma_tf32(s[1][ntl], Qa[1][2*g+1], u.z, u.w);
            }

        const float2* mrow2 = mrow2base + t * 32 + nh * 16;
        float sums[2][2] = {};
        #pragma unroll
        for (int ntl = 0; ntl < 4; ++ntl) {
            float2 mv = mrow2[ntl * 4 + q2];
            float mx = mv.x * LOG2E, my = mv.y * LOG2E;
            #pragma unroll
            for (int mt = 0; mt < 2; ++mt) {
                s[mt][ntl][0] = ex2(s[mt][ntl][0] + mx);
                s[mt][ntl][1] = ex2(s[mt][ntl][1] + my);
                s[mt][ntl][2] = ex2(s[mt][ntl][2] + mx);
                s[mt][ntl][3] = ex2(s[mt][ntl][3] + my);
                sums[mt][0] += s[mt][ntl][0] + s[mt][ntl][1];
                sums[mt][1] += s[mt][ntl][2] + s[mt][ntl][3];
            }
        }
        #pragma unroll
        for (int mt = 0; mt < 2; ++mt) {
            sums[mt][0] += __shfl_xor_sync(0xffffffffu, sums[mt][0], 1);
            sums[mt][0] += __shfl_xor_sync(0xffffffffu, sums[mt][0], 2);
            sums[mt][1] += __shfl_xor_sync(0xffffffffu, sums[mt][1], 1);
            sums[mt][1] += __shfl_xor_sync(0xffffffffu, sums[mt][1], 2);
            lr[mt][0] += sums[mt][0];
            lr[mt][1] += sums[mt][1];
        }

        __syncthreads();

        const uint32_t Pb = sbase + (uint32_t)((t & 1) ? KTILEB : 0);
        #pragma unroll
        for (int mt = 0; mt < 2; ++mt)
            #pragma unroll
            for (int ntl = 0; ntl < 4; ++ntl) {
                int row0 = mh * 32 + mt * 16 + r0;
                uint32_t colb = (uint32_t)(nh * 128 + ntl * 32 + q2 * 8);
                sts_v2(Pb + (uint32_t)row0 * 288 + (colb ^ xr_st),
                       s[mt][ntl][0], s[mt][ntl][1]);
                sts_v2(Pb + (uint32_t)(row0 + 8) * 288 + (colb ^ xr_st),
                       s[mt][ntl][2], s[mt][ntl][3]);
            }

        CP_WAIT1();
        __syncthreads();

        const uint32_t* Vb = sm + OFF_V / 4;
        #pragma unroll
        for (int g = 0; g < 4; ++g) {
            uint32_t A[2][2][4];
            #pragma unroll
            for (int mt = 0; mt < 2; ++mt)
                #pragma unroll
                for (int half = 0; half < 2; ++half) {
                    int ks = 2 * g + half;
                    uint32_t addr = Pb + (uint32_t)(mh * 32 + mt * 16 + lrow) * 288
                                  + (((uint32_t)(ks * 32 + lcb * 16)) ^ xr_ld);
                    uint32_t R[4];
                    ldsm_x4(R, addr);
                    A[mt][half][0] = R[0]; A[mt][half][1] = R[2];
                    A[mt][half][2] = R[1]; A[mt][half][3] = R[3];
                }
            #pragma unroll
            for (int nt = 0; nt < 4; ++nt) {
                uint4 v = *(const uint4*)&Vb[(nh * 32 + nt * 8 + r0) * KSTR + g * 16 + q2 * 4];
                mma_tf32(accO[0][nt], A[0][0], v.x, v.y);
                mma_tf32(accO[0][nt], A[0][1], v.z, v.w);
                mma_tf32(accO[1][nt], A[1][0], v.x, v.y);
                mma_tf32(accO[1][nt], A[1][1], v.z, v.w);
            }
        }

        __syncthreads();
        {
            int tv = (t + 1) & 31;
            const float* vs = vsrc0 + tv * 64;
            #pragma unroll
            for (int i = 0; i < 8; ++i)
                cpasync16(vdst + i * (8 * KSTR * 4), vs + i * 16384);
            CP_COMMIT();
            int tk = (t + 2) & 31;
            const float* ks = ksrc0 + tk * 4096;
            uint32_t kd = kdst0 + (uint32_t)((t & 1) ? KTILEB : 0);
            #pragma unroll
            for (int i = 0; i < 8; ++i)
                cpasync16(kd + i * (8 * KSTR * 4), ks + i * 512);
            CP_COMMIT();
        }
    }

    float* lrbuf = (float*)((char*)sm + OFF_LR);
    if (q2 == 0) {
        #pragma unroll
        for (int mt = 0; mt < 2; ++mt) {
            lrbuf[nh * 64 + mh * 32 + mt * 16 + r0]     = lr[mt][0];
            lrbuf[nh * 64 + mh * 32 + mt * 16 + r0 + 8] = lr[mt][1];
        }
    }
    __syncthreads();

    #pragma unroll
    for (int mt = 0; mt < 2; ++mt) {
        int rl = mh * 32 + mt * 16 + r0;
        float inv0 = 1.0f / (lrbuf[rl] + lrbuf[64 + rl]);
        float inv1 = 1.0f / (lrbuf[rl + 8] + lrbuf[64 + rl + 8]);
        int row = qbase + rl;
        #pragma unroll
        for (int nt = 0; nt < 4; ++nt) {
            int dcol = nh * 32 + nt * 8 + 2 * q2;
            float2 o0 = { accO[mt][nt][0] * inv0, accO[mt][nt][1] * inv0 };
            *(float2*)(out + ((size_t)(b * SEQ + row)) * HIDDEN + h * 64 + dcol) = o0;
            float2 o1 = { accO[mt][nt][2] * inv1, accO[mt][nt][3] * inv1 };
            *(float2*)(out + ((size_t)(b * SEQ + row + 8)) * HIDDEN + h * 64 + dcol) = o1;
        }
    }
}

extern "C" void kernel_launch(void* const* d_in, const int* in_sizes, int n_in,
                              void* d_out, int out_size) {
    const float* x   = (const float*)d_in[0];
    const float* msk = (const float*)d_in[1];
    const float* Wq  = (const float*)d_in[2];
    const float* bq  = (const float*)d_in[3];
    const float* Wk  = (const float*)d_in[4];
    const float* bk  = (const float*)d_in[5];
    const float* Wv  = (const float*)d_in[6];
    const float* bv  = (const float*)d_in[7];
    float* out = (float*)d_out;

    cudaFuncSetAttribute(attn_kernel, cudaFuncAttributeMaxDynamicSharedMemorySize,
                         SMEMB);

    qkv_proj_kernel<<<dim3(M_TOTAL / 128, HIDDEN / 64, 3), 256>>>(x, Wq, bq, Wk, bk, Wv, bv);
    attn_kernel<<<dim3(SEQ / 64, BATCH * NUM_HEADS), 128, SMEMB>>>(msk, out);
}

// round 13
// speedup vs baseline: 1.2347x; 1.2347x over previous
#include <cuda_runtime.h>
#include <stdint.h>

#define NUM_HEADS 12
#define HEAD_DIM  64
#define HIDDEN    768
#define BATCH     2
#define SEQ       2048
#define M_TOTAL   (BATCH*SEQ)   // 4096
#define LOG2E     1.44269504f

// Q,K in [B,H,S,d] with d permuted within 16-groups (pos16); V TRANSPOSED
// [B,H,d,S] with key permuted within 16-groups. All tf32-rounded f32;
// Q pre-scaled by 0.125*log2(e).
__device__ float g_qkv[3][BATCH*NUM_HEADS*SEQ*HEAD_DIM];

__device__ __forceinline__ uint32_t f2tf32(float f) {
    uint32_t u;
    asm("cvt.rna.tf32.f32 %0, %1;" : "=r"(u) : "f"(f));
    return u;
}

__device__ __forceinline__ float ex2(float f) {
    float r;
    asm("ex2.approx.f32 %0, %1;" : "=f"(r) : "f"(f));
    return r;
}

__device__ __forceinline__ void mma_tf32(float c[4], const uint32_t a[4],
                                         uint32_t b0, uint32_t b1) {
    asm volatile(
        "mma.sync.aligned.m16n8k8.row.col.f32.tf32.tf32.f32 "
        "{%0,%1,%2,%3}, {%4,%5,%6,%7}, {%8,%9}, {%0,%1,%2,%3};"
        : "+f"(c[0]), "+f"(c[1]), "+f"(c[2]), "+f"(c[3])
        : "r"(a[0]), "r"(a[1]), "r"(a[2]), "r"(a[3]), "r"(b0), "r"(b1));
}

__device__ __forceinline__ void ldsm_x4(uint32_t r[4], uint32_t addr) {
    asm volatile("ldmatrix.sync.aligned.m8n8.x4.shared.b16 {%0,%1,%2,%3}, [%4];"
        : "=r"(r[0]), "=r"(r[1]), "=r"(r[2]), "=r"(r[3]) : "r"(addr));
}

__device__ __forceinline__ void sts_v2(uint32_t addr, float a, float b) {
    asm volatile("st.shared.v2.f32 [%0], {%1,%2};" :: "r"(addr), "f"(a), "f"(b));
}

__device__ __forceinline__ void cpasync16(uint32_t dst, const void* src) {
    asm volatile("cp.async.cg.shared.global [%0], [%1], 16;" :: "r"(dst), "l"(src));
}
#define CP_COMMIT() asm volatile("cp.async.commit_group;")
#define CP_WAIT1()  asm volatile("cp.async.wait_group 1;")
#define CP_WAIT2()  asm volatile("cp.async.wait_group 2;")

// physical position of logical index r within its 16-group
__device__ __forceinline__ int pos16(int r) {
    return 4 * (r & 3) + 2 * (r >> 3) + ((r >> 2) & 1);
}
__device__ __forceinline__ int perm16(int d) {
    return (d & ~15) | pos16(d & 15);
}

// ---------------------------------------------------------------------------
// QKV projection (R10 structure, BN doubled): BM=128, BN=128, BK=32.
// 256 threads, 8 warps = 4(m) x 2(n); warp tile m32 x n64.
// Grid (32, 6, 3) = 576 CTAs -> ~2.0 waves at 2 CTAs/SM.
// Numerics identical to R10 (cvt.rna at STS, same k-order).
// ---------------------------------------------------------------------------
__global__ __launch_bounds__(256, 2) void qkv_proj_kernel(
    const float* __restrict__ x,
    const float* __restrict__ Wq, const float* __restrict__ bq,
    const float* __restrict__ Wk, const float* __restrict__ bk,
    const float* __restrict__ Wv, const float* __restrict__ bv)
{
    const int z = blockIdx.z;
    const float* Wp   = (z == 0) ? Wq : (z == 1) ? Wk : Wv;
    const float* bias = (z == 0) ? bq : (z == 1) ? bk : bv;

    __shared__ uint32_t Xs[128 * 36];   // [m][k], stride 36
    __shared__ uint32_t Ws[32 * 136];   // [k][n], stride 136 (==8 mod 32)

    const int tid  = threadIdx.x;
    const int lane = tid & 31;
    const int warp = tid >> 5;
    const int wm = warp >> 1;       // 0..3  (m32 tile)
    const int wn = warp & 1;        // 0..1  (n64 half)
    const int m0 = blockIdx.x * 128;
    const int n0 = blockIdx.y * 128;
    const int r0 = lane >> 2;
    const int q2 = lane & 3;

    const int xr_r = tid >> 3, xr_c = (tid & 7) * 4;   // X: 128x32
    const int wr_r = tid >> 3, wr_c4 = tid & 7;        // W: 32x128 (4 f4/thread)

    float4 xr[4], wr[4];
    #pragma unroll
    for (int it = 0; it < 4; ++it)
        xr[it] = *(const float4*)(x + (size_t)(m0 + xr_r + it * 32) * HIDDEN + xr_c);
    #pragma unroll
    for (int it = 0; it < 4; ++it)
        wr[it] = *(const float4*)(Wp + (size_t)wr_r * HIDDEN + n0 + (wr_c4 + 8 * it) * 4);

    float acc[2][8][4] = {};

    for (int k0 = 0; k0 < HIDDEN; k0 += 32) {
        #pragma unroll
        for (int it = 0; it < 4; ++it) {
            uint4 u = { f2tf32(xr[it].x), f2tf32(xr[it].y), f2tf32(xr[it].z), f2tf32(xr[it].w) };
            *(uint4*)&Xs[(xr_r + it * 32) * 36 + xr_c] = u;
        }
        #pragma unroll
        for (int it = 0; it < 4; ++it) {
            uint4 u = { f2tf32(wr[it].x), f2tf32(wr[it].y), f2tf32(wr[it].z), f2tf32(wr[it].w) };
            *(uint4*)&Ws[wr_r * 136 + (wr_c4 + 8 * it) * 4] = u;
        }
        __syncthreads();

        if (k0 + 32 < HIDDEN) {
            #pragma unroll
            for (int it = 0; it < 4; ++it)
                xr[it] = *(const float4*)(x + (size_t)(m0 + xr_r + it * 32) * HIDDEN + k0 + 32 + xr_c);
            #pragma unroll
            for (int it = 0; it < 4; ++it)
                wr[it] = *(const float4*)(Wp + (size_t)(k0 + 32 + wr_r) * HIDDEN + n0 + (wr_c4 + 8 * it) * 4);
        }

        #pragma unroll
        for (int ks = 0; ks < 4; ++ks) {
            uint32_t a[2][4];
            #pragma unroll
            for (int mt = 0; mt < 2; ++mt) {
                int R = wm * 32 + mt * 16 + r0;
                int C = ks * 8 + q2;
                a[mt][0] = Xs[R * 36 + C];
                a[mt][1] = Xs[(R + 8) * 36 + C];
                a[mt][2] = Xs[R * 36 + C + 4];
                a[mt][3] = Xs[(R + 8) * 36 + C + 4];
            }
            #pragma unroll
            for (int nt = 0; nt < 8; ++nt) {
                int Kr = ks * 8 + q2;
                int Cn = wn * 64 + nt * 8 + r0;
                uint32_t b0 = Ws[Kr * 136 + Cn];
                uint32_t b1 = Ws[(Kr + 4) * 136 + Cn];
                mma_tf32(acc[0][nt], a[0], b0, b1);
                mma_tf32(acc[1][nt], a[1], b0, b1);
            }
        }
        __syncthreads();
    }

    const int h2 = blockIdx.y * 2 + wn;   // actual head for this warp's columns
    if (z != 2) {
        float* out = g_qkv[z];
        const float scale = (z == 0) ? 0.125f * LOG2E : 1.0f;
        #pragma unroll
        for (int mt = 0; mt < 2; ++mt)
            #pragma unroll
            for (int nt = 0; nt < 8; ++nt) {
                int din = nt * 8 + 2 * q2;           // 0..63 within head
                int d0 = perm16(din);
                int d1 = perm16(din + 1);
                float b0 = bias[n0 + wn * 64 + din];
                float b1 = bias[n0 + wn * 64 + din + 1];
                #pragma unroll
                for (int half = 0; half < 2; ++half) {
                    int m  = m0 + wm * 32 + mt * 16 + r0 + half * 8;
                    int bI = m >> 11;
                    int sI = m & 2047;
                    float* po = out + (((size_t)(bI * NUM_HEADS + h2)) * SEQ + sI) * HEAD_DIM;
                    po[d0] = __uint_as_float(f2tf32((acc[mt][nt][half * 2 + 0] + b0) * scale));
                    po[d1] = __uint_as_float(f2tf32((acc[mt][nt][half * 2 + 1] + b1) * scale));
                }
            }
    } else {
        // V: transposed store [B,H,d,S], key index permuted within 16-groups
        float* outT = g_qkv[2];
        #pragma unroll
        for (int mt = 0; mt < 2; ++mt)
            #pragma unroll
            for (int nt = 0; nt < 8; ++nt) {
                int din = nt * 8 + 2 * q2;
                float b0 = bias[n0 + wn * 64 + din];
                float b1 = bias[n0 + wn * 64 + din + 1];
                #pragma unroll
                for (int half = 0; half < 2; ++half) {
                    int m  = m0 + wm * 32 + mt * 16 + r0 + half * 8;
                    int bI = m >> 11;
                    int sI = m & 2047;
                    int sp = (sI & ~15) | pos16(sI & 15);
                    size_t base = (size_t)(bI * NUM_HEADS + h2) * 64;
                    outT[(base + din) * SEQ + sp] =
                        __uint_as_float(f2tf32(acc[mt][nt][half * 2 + 0] + b0));
                    outT[(base + din + 1) * SEQ + sp] =
                        __uint_as_float(f2tf32(acc[mt][nt][half * 2 + 1] + b1));
                }
            }
    }
}

// ---------------------------------------------------------------------------
// Flash attention (R10, unchanged): all-tf32, Br=64, 4 warps split
// (mh, nh); QK m32xn32, PV m32xd32; K double-buffered, V single-buffered;
// P through dead K(t) buffer via STS.64 + ldmatrix.b16.
// smem 61952B -> 3 CTAs/SM.
// ---------------------------------------------------------------------------
#define KSTR   80
#define KTILEB 20480      // 64*80*4
#define OFF_V  40960
#define OFF_LR 61440
#define SMEMB  61952

__global__ __launch_bounds__(128, 3) void attn_kernel(
    const float* __restrict__ mask,   // [B,1,1,S]
    float* __restrict__ out)          // [B,S,HIDDEN]
{
    extern __shared__ __align__(16) uint32_t sm[];

    const int tid  = threadIdx.x;
    const int lane = tid & 31;
    const int warp = tid >> 5;
    const int r0 = lane >> 2;
    const int q2 = lane & 3;
    const int mh = warp >> 1;
    const int nh = warp & 1;
    const int qbase = blockIdx.x * 64;
    const int bh = blockIdx.y;
    const int b  = bh / NUM_HEADS;
    const int h  = bh - b * NUM_HEADS;

    const float* Qg = g_qkv[0] + (size_t)bh * SEQ * 64;
    const float* Kg = g_qkv[1] + (size_t)bh * SEQ * 64;
    const float* Vg = g_qkv[2] + (size_t)bh * 64 * SEQ;
    const float2* mrow2base = (const float2*)(mask + (size_t)b * SEQ);

    const int rowk = tid >> 4;
    const int ch4  = (tid & 15) * 4;
    const uint32_t sbase = (uint32_t)__cvta_generic_to_shared(sm);
    const uint32_t kdst0 = sbase + (uint32_t)(rowk * KSTR + ch4) * 4;
    const uint32_t vdst  = sbase + OFF_V + (uint32_t)(rowk * KSTR + ch4) * 4;
    const float* ksrc0 = Kg + rowk * 64 + ch4;
    const float* vsrc0 = Vg + rowk * 2048 + ch4;

    #pragma unroll
    for (int i = 0; i < 8; ++i)
        cpasync16(kdst0 + i * (8 * KSTR * 4), ksrc0 + i * 512);
    CP_COMMIT();
    #pragma unroll
    for (int i = 0; i < 8; ++i)
        cpasync16(vdst + i * (8 * KSTR * 4), vsrc0 + i * 16384);
    CP_COMMIT();
    #pragma unroll
    for (int i = 0; i < 8; ++i)
        cpasync16(kdst0 + KTILEB + i * (8 * KSTR * 4), ksrc0 + 4096 + i * 512);
    CP_COMMIT();

    uint32_t Qa[2][8][4];
    #pragma unroll
    for (int mt = 0; mt < 2; ++mt) {
        const float* qp = Qg + (size_t)(qbase + mh * 32 + mt * 16 + r0) * 64;
        #pragma unroll
        for (int g = 0; g < 4; ++g) {
            float4 lo = *(const float4*)(qp + g * 16 + q2 * 4);
            float4 hi = *(const float4*)(qp + 512 + g * 16 + q2 * 4);
            Qa[mt][2*g][0]   = __float_as_uint(lo.x);
            Qa[mt][2*g][2]   = __float_as_uint(lo.y);
            Qa[mt][2*g+1][0] = __float_as_uint(lo.z);
            Qa[mt][2*g+1][2] = __float_as_uint(lo.w);
            Qa[mt][2*g][1]   = __float_as_uint(hi.x);
            Qa[mt][2*g][3]   = __float_as_uint(hi.y);
            Qa[mt][2*g+1][1] = __float_as_uint(hi.z);
            Qa[mt][2*g+1][3] = __float_as_uint(hi.w);
        }
    }

    float accO[2][4][4] = {};
    float lr[2][2] = {};

    const int  lrow  = (lane & 7) | ((lane >> 1) & 8);
    const int  lcb   = (lane >> 3) & 1;
    const uint32_t xr_st = (uint32_t)((r0 & 4) << 2);
    const uint32_t xr_ld = (uint32_t)((lrow & 4) << 2);

    for (int t = 0; t < 32; ++t) {
        CP_WAIT2();
        __syncthreads();

        const uint32_t* Kb = sm + ((t & 1) ? KTILEB : 0) / 4;
        float s[2][4][4] = {};
        #pragma unroll
        for (int g = 0; g < 4; ++g)
            #pragma unroll
            for (int ntl = 0; ntl < 4; ++ntl) {
                uint4 u = *(const uint4*)&Kb[(nh * 32 + ntl * 8 + r0) * KSTR + g * 16 + q2 * 4];
                mma_tf32(s[0][ntl], Qa[0][2*g],   u.x, u.y);
                mma_tf32(s[0][ntl], Qa[0][2*g+1], u.z, u.w);
                mma_tf32(s[1][ntl], Qa[1][2*g],   u.x, u.y);
                mma_tf32(s[1][ntl], Qa[1][2*g+1], u.z, u.w);
            }

        const float2* mrow2 = mrow2base + t * 32 + nh * 16;
        float sums[2][2] = {};
        #pragma unroll
        for (int ntl = 0; ntl < 4; ++ntl) {
            float2 mv = mrow2[ntl * 4 + q2];
            float mx = mv.x * LOG2E, my = mv.y * LOG2E;
            #pragma unroll
            for (int mt = 0; mt < 2; ++mt) {
                s[mt][ntl][0] = ex2(s[mt][ntl][0] + mx);
                s[mt][ntl][1] = ex2(s[mt][ntl][1] + my);
                s[mt][ntl][2] = ex2(s[mt][ntl][2] + mx);
                s[mt][ntl][3] = ex2(s[mt][ntl][3] + my);
                sums[mt][0] += s[mt][ntl][0] + s[mt][ntl][1];
                sums[mt][1] += s[mt][ntl][2] + s[mt][ntl][3];
            }
        }
        #pragma unroll
        for (int mt = 0; mt < 2; ++mt) {
            sums[mt][0] += __shfl_xor_sync(0xffffffffu, sums[mt][0], 1);
            sums[mt][0] += __shfl_xor_sync(0xffffffffu, sums[mt][0], 2);
            sums[mt][1] += __shfl_xor_sync(0xffffffffu, sums[mt][1], 1);
            sums[mt][1] += __shfl_xor_sync(0xffffffffu, sums[mt][1], 2);
            lr[mt][0] += sums[mt][0];
            lr[mt][1] += sums[mt][1];
        }

        __syncthreads();

        const uint32_t Pb = sbase + (uint32_t)((t & 1) ? KTILEB : 0);
        #pragma unroll
        for (int mt = 0; mt < 2; ++mt)
            #pragma unroll
            for (int ntl = 0; ntl < 4; ++ntl) {
                int row0 = mh * 32 + mt * 16 + r0;
                uint32_t colb = (uint32_t)(nh * 128 + ntl * 32 + q2 * 8);
                sts_v2(Pb + (uint32_t)row0 * 288 + (colb ^ xr_st),
                       s[mt][ntl][0], s[mt][ntl][1]);
                sts_v2(Pb + (uint32_t)(row0 + 8) * 288 + (colb ^ xr_st),
                       s[mt][ntl][2], s[mt][ntl][3]);
            }

        CP_WAIT1();
        __syncthreads();

        const uint32_t* Vb = sm + OFF_V / 4;
        #pragma unroll
        for (int g = 0; g < 4; ++g) {
            uint32_t A[2][2][4];
            #pragma unroll
            for (int mt = 0; mt < 2; ++mt)
                #pragma unroll
                for (int half = 0; half < 2; ++half) {
                    int ks = 2 * g + half;
                    uint32_t addr = Pb + (uint32_t)(mh * 32 + mt * 16 + lrow) * 288
                                  + (((uint32_t)(ks * 32 + lcb * 16)) ^ xr_ld);
                    uint32_t R[4];
                    ldsm_x4(R, addr);
                    A[mt][half][0] = R[0]; A[mt][half][1] = R[2];
                    A[mt][half][2] = R[1]; A[mt][half][3] = R[3];
                }
            #pragma unroll
            for (int nt = 0; nt < 4; ++nt) {
                uint4 v = *(const uint4*)&Vb[(nh * 32 + nt * 8 + r0) * KSTR + g * 16 + q2 * 4];
                mma_tf32(accO[0][nt], A[0][0], v.x, v.y);
                mma_tf32(accO[0][nt], A[0][1], v.z, v.w);
                mma_tf32(accO[1][nt], A[1][0], v.x, v.y);
                mma_tf32(accO[1][nt], A[1][1], v.z, v.w);
            }
        }

        __syncthreads();
        {
            int tv = (t + 1) & 31;
            const float* vs = vsrc0 + tv * 64;
            #pragma unroll
            for (int i = 0; i < 8; ++i)
                cpasync16(vdst + i * (8 * KSTR * 4), vs + i * 16384);
            CP_COMMIT();
            int tk = (t + 2) & 31;
            const float* ks = ksrc0 + tk * 4096;
            uint32_t kd = kdst0 + (uint32_t)((t & 1) ? KTILEB : 0);
            #pragma unroll
            for (int i = 0; i < 8; ++i)
                cpasync16(kd + i * (8 * KSTR * 4), ks + i * 512);
            CP_COMMIT();
        }
    }

    float* lrbuf = (float*)((char*)sm + OFF_LR);
    if (q2 == 0) {
        #pragma unroll
        for (int mt = 0; mt < 2; ++mt) {
            lrbuf[nh * 64 + mh * 32 + mt * 16 + r0]     = lr[mt][0];
            lrbuf[nh * 64 + mh * 32 + mt * 16 + r0 + 8] = lr[mt][1];
        }
    }
    __syncthreads();

    #pragma unroll
    for (int mt = 0; mt < 2; ++mt) {
        int rl = mh * 32 + mt * 16 + r0;
        float inv0 = 1.0f / (lrbuf[rl] + lrbuf[64 + rl]);
        float inv1 = 1.0f / (lrbuf[rl + 8] + lrbuf[64 + rl + 8]);
        int row = qbase + rl;
        #pragma unroll
        for (int nt = 0; nt < 4; ++nt) {
            int dcol = nh * 32 + nt * 8 + 2 * q2;
            float2 o0 = { accO[mt][nt][0] * inv0, accO[mt][nt][1] * inv0 };
            *(float2*)(out + ((size_t)(b * SEQ + row)) * HIDDEN + h * 64 + dcol) = o0;
            float2 o1 = { accO[mt][nt][2] * inv1, accO[mt][nt][3] * inv1 };
            *(float2*)(out + ((size_t)(b * SEQ + row + 8)) * HIDDEN + h * 64 + dcol) = o1;
        }
    }
}

extern "C" void kernel_launch(void* const* d_in, const int* in_sizes, int n_in,
                              void* d_out, int out_size) {
    const float* x   = (const float*)d_in[0];
    const float* msk = (const float*)d_in[1];
    const float* Wq  = (const float*)d_in[2];
    const float* bq  = (const float*)d_in[3];
    const float* Wk  = (const float*)d_in[4];
    const float* bk  = (const float*)d_in[5];
    const float* Wv  = (const float*)d_in[6];
    const float* bv  = (const float*)d_in[7];
    float* out = (float*)d_out;

    cudaFuncSetAttribute(attn_kernel, cudaFuncAttributeMaxDynamicSharedMemorySize,
                         SMEMB);

    qkv_proj_kernel<<<dim3(M_TOTAL / 128, HIDDEN / 128, 3), 256>>>(x, Wq, bq, Wk, bk, Wv, bv);
    attn_kernel<<<dim3(SEQ / 64, BATCH * NUM_HEADS), 128, SMEMB>>>(msk, out);
}